// round 6
// baseline (speedup 1.0000x reference)
#include <cuda_runtime.h>

#define TOKENS 8192
#define INDIM  256
#define MDIM   512
#define QKV3   1536
#define NHEADS 8
#define DHEAD  64
#define NSEQ   2048
#define CATD   768
#define SCALE  0.125f

// ---------------- scratch (device globals; no allocations allowed) --------
__device__ float g_qkv [TOKENS * QKV3];   // 50.3 MB
__device__ float g_attn[TOKENS * MDIM];   // 16.8 MB
__device__ float g_cat [TOKENS * CATD];   // 25.2 MB

// ---------------- generic tiled fp32 GEMM: C = A @ B + bias ---------------
// A: [M,K] row-major (lda), B: [K,N] row-major (ldb), C: [M,N] (ldc)
// BM=BN=64, BK=16, 256 threads, 4x4 per thread.
__global__ __launch_bounds__(256) void gemm_bias(
    const float* __restrict__ A, int lda,
    const float* __restrict__ B, int ldb,
    const float* __restrict__ bias,
    float* __restrict__ C, int ldc,
    int M, int N, int K)
{
    __shared__ float As[16][65];   // transposed: As[k][m], padded
    __shared__ float Bs[16][64];   // Bs[k][n]

    const int tid = threadIdx.x;
    const int tr  = tid >> 4;      // 0..15 -> output rows tr*4..tr*4+3
    const int tc  = tid & 15;      // 0..15 -> output cols tc*4..tc*4+3
    const int m0  = blockIdx.y * 64;
    const int n0  = blockIdx.x * 64;

    // A tile load: 64 rows x 16 cols, one float4 per thread
    const int a_row = tid >> 2;          // 0..63
    const int a_col = (tid & 3) * 4;     // 0,4,8,12
    // B tile load: 16 rows x 64 cols, one float4 per thread
    const int b_row = tid >> 4;          // 0..15
    const int b_col = (tid & 15) * 4;    // 0..60

    const float* Aptr = A + (size_t)(m0 + a_row) * lda + a_col;
    const float* Bptr = B + (size_t)b_row * ldb + n0 + b_col;

    float acc[4][4];
#pragma unroll
    for (int i = 0; i < 4; i++)
#pragma unroll
        for (int j = 0; j < 4; j++) acc[i][j] = 0.f;

    for (int k0 = 0; k0 < K; k0 += 16) {
        float4 av = *(const float4*)(Aptr + k0);
        float4 bv = *(const float4*)(Bptr + (size_t)k0 * ldb);
        As[a_col + 0][a_row] = av.x;
        As[a_col + 1][a_row] = av.y;
        As[a_col + 2][a_row] = av.z;
        As[a_col + 3][a_row] = av.w;
        *(float4*)&Bs[b_row][b_col] = bv;
        __syncthreads();

#pragma unroll
        for (int kk = 0; kk < 16; kk++) {
            float a0 = As[kk][tr * 4 + 0];
            float a1 = As[kk][tr * 4 + 1];
            float a2 = As[kk][tr * 4 + 2];
            float a3 = As[kk][tr * 4 + 3];
            float4 b4 = *(const float4*)&Bs[kk][tc * 4];
            acc[0][0] += a0 * b4.x; acc[0][1] += a0 * b4.y; acc[0][2] += a0 * b4.z; acc[0][3] += a0 * b4.w;
            acc[1][0] += a1 * b4.x; acc[1][1] += a1 * b4.y; acc[1][2] += a1 * b4.z; acc[1][3] += a1 * b4.w;
            acc[2][0] += a2 * b4.x; acc[2][1] += a2 * b4.y; acc[2][2] += a2 * b4.z; acc[2][3] += a2 * b4.w;
            acc[3][0] += a3 * b4.x; acc[3][1] += a3 * b4.y; acc[3][2] += a3 * b4.z; acc[3][3] += a3 * b4.w;
        }
        __syncthreads();
    }

    const float bx = bias[n0 + tc * 4 + 0];
    const float by = bias[n0 + tc * 4 + 1];
    const float bz = bias[n0 + tc * 4 + 2];
    const float bw = bias[n0 + tc * 4 + 3];
#pragma unroll
    for (int i = 0; i < 4; i++) {
        float4 o;
        o.x = acc[i][0] + bx;
        o.y = acc[i][1] + by;
        o.z = acc[i][2] + bz;
        o.w = acc[i][3] + bw;
        *(float4*)&C[(size_t)(m0 + tr * 4 + i) * ldc + n0 + tc * 4] = o;
    }
}

// ---------------- flash attention (fp32, 64x64 tiles) ---------------------
// qkv row layout: [ q(512) | k(512) | v(512) ], head h at col h*64.
// grid: (NSEQ/64, NHEADS, B), 256 threads. Online softmax.
__global__ __launch_bounds__(256) void attn_kernel(
    const float* __restrict__ qkv, float* __restrict__ outp)
{
    extern __shared__ float sm[];
    float* Qs = sm;                 // [64][65]
    float* KP = sm + 64 * 65;       // K tile, then reused as P tile [64][65]
    float* Vs = sm + 2 * 64 * 65;   // [64][65]

    const int tid = threadIdx.x;
    const int tr  = tid >> 4;       // rows tr*4..+3
    const int tc  = tid & 15;       // cols tc*4..+3
    const int q0  = blockIdx.x * 64;
    const int h   = blockIdx.y;
    const int b   = blockIdx.z;
    const size_t rowbase = (size_t)b * NSEQ;

    // ---- load Q tile [64 x 64] ----
    const float* qptr = qkv + (rowbase + q0) * QKV3 + h * DHEAD;
#pragma unroll
    for (int u = 0; u < 4; u++) {
        int idx = tid + u * 256;
        int r = idx >> 4, c = (idx & 15) * 4;
        float4 v = *(const float4*)(qptr + (size_t)r * QKV3 + c);
        Qs[r * 65 + c + 0] = v.x; Qs[r * 65 + c + 1] = v.y;
        Qs[r * 65 + c + 2] = v.z; Qs[r * 65 + c + 3] = v.w;
    }

    float m[4], l[4], acc[4][4];
#pragma unroll
    for (int i = 0; i < 4; i++) {
        m[i] = -1e30f; l[i] = 0.f;
#pragma unroll
        for (int j = 0; j < 4; j++) acc[i][j] = 0.f;
    }
    __syncthreads();

    for (int t = 0; t < NSEQ; t += 64) {
        // ---- load K and V tiles ----
        const float* kptr = qkv + (rowbase + t) * QKV3 + MDIM + h * DHEAD;
        const float* vptr = qkv + (rowbase + t) * QKV3 + 2 * MDIM + h * DHEAD;
#pragma unroll
        for (int u = 0; u < 4; u++) {
            int idx = tid + u * 256;
            int r = idx >> 4, c = (idx & 15) * 4;
            float4 kv4 = *(const float4*)(kptr + (size_t)r * QKV3 + c);
            KP[r * 65 + c + 0] = kv4.x; KP[r * 65 + c + 1] = kv4.y;
            KP[r * 65 + c + 2] = kv4.z; KP[r * 65 + c + 3] = kv4.w;
            float4 vv4 = *(const float4*)(vptr + (size_t)r * QKV3 + c);
            Vs[r * 65 + c + 0] = vv4.x; Vs[r * 65 + c + 1] = vv4.y;
            Vs[r * 65 + c + 2] = vv4.z; Vs[r * 65 + c + 3] = vv4.w;
        }
        __syncthreads();

        // ---- S = Q @ K^T (4x4 per thread) ----
        float s[4][4];
#pragma unroll
        for (int i = 0; i < 4; i++)
#pragma unroll
            for (int j = 0; j < 4; j++) s[i][j] = 0.f;

#pragma unroll 8
        for (int d = 0; d < 64; d++) {
            float a0 = Qs[(tr * 4 + 0) * 65 + d];
            float a1 = Qs[(tr * 4 + 1) * 65 + d];
            float a2 = Qs[(tr * 4 + 2) * 65 + d];
            float a3 = Qs[(tr * 4 + 3) * 65 + d];
            float b0 = KP[(tc * 4 + 0) * 65 + d];
            float b1 = KP[(tc * 4 + 1) * 65 + d];
            float b2 = KP[(tc * 4 + 2) * 65 + d];
            float b3 = KP[(tc * 4 + 3) * 65 + d];
            s[0][0] += a0 * b0; s[0][1] += a0 * b1; s[0][2] += a0 * b2; s[0][3] += a0 * b3;
            s[1][0] += a1 * b0; s[1][1] += a1 * b1; s[1][2] += a1 * b2; s[1][3] += a1 * b3;
            s[2][0] += a2 * b0; s[2][1] += a2 * b1; s[2][2] += a2 * b2; s[2][3] += a2 * b3;
            s[3][0] += a3 * b0; s[3][1] += a3 * b1; s[3][2] += a3 * b2; s[3][3] += a3 * b3;
        }

        // ---- online softmax over rows (16 lanes share one row group) ----
#pragma unroll
        for (int i = 0; i < 4; i++) {
#pragma unroll
            for (int j = 0; j < 4; j++) s[i][j] *= SCALE;
            float tm = fmaxf(fmaxf(s[i][0], s[i][1]), fmaxf(s[i][2], s[i][3]));
#pragma unroll
            for (int off = 8; off > 0; off >>= 1)
                tm = fmaxf(tm, __shfl_xor_sync(0xffffffffu, tm, off));
            float mn = fmaxf(m[i], tm);
            float al = __expf(m[i] - mn);
            float rs = 0.f;
#pragma unroll
            for (int j = 0; j < 4; j++) {
                s[i][j] = __expf(s[i][j] - mn);
                rs += s[i][j];
            }
#pragma unroll
            for (int off = 8; off > 0; off >>= 1)
                rs += __shfl_xor_sync(0xffffffffu, rs, off);
            l[i] = l[i] * al + rs;
#pragma unroll
            for (int j = 0; j < 4; j++) acc[i][j] *= al;
            m[i] = mn;
        }

        __syncthreads();   // all K reads done before overwriting with P
#pragma unroll
        for (int i = 0; i < 4; i++)
#pragma unroll
            for (int j = 0; j < 4; j++)
                KP[(tr * 4 + i) * 65 + tc * 4 + j] = s[i][j];
        __syncthreads();

        // ---- O += P @ V ----
#pragma unroll 8
        for (int kv = 0; kv < 64; kv++) {
            float p0 = KP[(tr * 4 + 0) * 65 + kv];
            float p1 = KP[(tr * 4 + 1) * 65 + kv];
            float p2 = KP[(tr * 4 + 2) * 65 + kv];
            float p3 = KP[(tr * 4 + 3) * 65 + kv];
            float v0 = Vs[kv * 65 + tc * 4 + 0];
            float v1 = Vs[kv * 65 + tc * 4 + 1];
            float v2 = Vs[kv * 65 + tc * 4 + 2];
            float v3 = Vs[kv * 65 + tc * 4 + 3];
            acc[0][0] += p0 * v0; acc[0][1] += p0 * v1; acc[0][2] += p0 * v2; acc[0][3] += p0 * v3;
            acc[1][0] += p1 * v0; acc[1][1] += p1 * v1; acc[1][2] += p1 * v2; acc[1][3] += p1 * v3;
            acc[2][0] += p2 * v0; acc[2][1] += p2 * v1; acc[2][2] += p2 * v2; acc[2][3] += p2 * v3;
            acc[3][0] += p3 * v0; acc[3][1] += p3 * v1; acc[3][2] += p3 * v2; acc[3][3] += p3 * v3;
        }
        __syncthreads();
    }

    // ---- epilogue: normalize + write [b, n, h*64 + c] ----
    float* obase = outp + (rowbase + q0) * MDIM + h * DHEAD;
#pragma unroll
    for (int i = 0; i < 4; i++) {
        float inv = 1.0f / l[i];
        float4 o;
        o.x = acc[i][0] * inv;
        o.y = acc[i][1] * inv;
        o.z = acc[i][2] * inv;
        o.w = acc[i][3] * inv;
        *(float4*)(obase + (size_t)(tr * 4 + i) * MDIM + tc * 4) = o;
    }
}

// ---------------- IBPP branch: silu(xr @ w_in + b_in) @ w_out + b_out -----
// one thread per (token, row-of-16); writes into g_cat cols [512, 768)
__global__ __launch_bounds__(256) void ib_kernel(
    const float* __restrict__ x,
    const float* __restrict__ w_in, const float* __restrict__ b_in,
    const float* __restrict__ w_out, const float* __restrict__ b_out,
    float* __restrict__ cat)
{
    __shared__ float wi[16][16], wo[16][16], bi[16], bo[16];
    const int tid = threadIdx.x;
    wi[tid >> 4][tid & 15] = w_in[tid];
    wo[tid >> 4][tid & 15] = w_out[tid];
    if (tid < 16) { bi[tid] = b_in[tid]; bo[tid] = b_out[tid]; }
    __syncthreads();

    const int gid = blockIdx.x * 256 + tid;
    const int token = gid >> 4;
    const int i = gid & 15;

    const float* xr = x + (size_t)token * INDIM + i * 16;
    float xv[16];
#pragma unroll
    for (int k = 0; k < 16; k++) xv[k] = xr[k];

    float t1[16];
#pragma unroll
    for (int j = 0; j < 16; j++) {
        float s = bi[j];
#pragma unroll
        for (int k = 0; k < 16; k++) s += xv[k] * wi[k][j];
        t1[j] = s / (1.0f + __expf(-s));   // silu
    }

    float* o = cat + (size_t)token * CATD + MDIM + i * 16;
#pragma unroll
    for (int j = 0; j < 16; j++) {
        float s = bo[j];
#pragma unroll
        for (int k = 0; k < 16; k++) s += t1[k] * wo[k][j];
        o[j] = s;
    }
}

// ---------------- launch ---------------------------------------------------
extern "C" void kernel_launch(void* const* d_in, const int* in_sizes, int n_in,
                              void* d_out, int out_size)
{
    const float* x       = (const float*)d_in[0];
    const float* w_qkv   = (const float*)d_in[1];
    const float* b_qkv   = (const float*)d_in[2];
    const float* w_in    = (const float*)d_in[3];
    const float* b_in    = (const float*)d_in[4];
    const float* w_out   = (const float*)d_in[5];
    const float* b_out   = (const float*)d_in[6];
    const float* w_merge = (const float*)d_in[7];
    const float* b_merge = (const float*)d_in[8];
    const float* w_proj  = (const float*)d_in[9];
    const float* b_proj  = (const float*)d_in[10];
    float* out = (float*)d_out;

    float *qkv, *attn, *cat;
    cudaGetSymbolAddress((void**)&qkv,  g_qkv);
    cudaGetSymbolAddress((void**)&attn, g_attn);
    cudaGetSymbolAddress((void**)&cat,  g_cat);

    const int attn_smem = 3 * 64 * 65 * (int)sizeof(float);   // 49920 B
    cudaFuncSetAttribute(attn_kernel,
                         cudaFuncAttributeMaxDynamicSharedMemorySize, attn_smem);

    // 1) QKV = x @ w_qkv + b_qkv          [8192,1536] K=256
    gemm_bias<<<dim3(QKV3 / 64, TOKENS / 64), 256>>>(
        x, INDIM, w_qkv, QKV3, b_qkv, qkv, QKV3, TOKENS, QKV3, INDIM);

    // 2) flash attention -> g_attn        [8192,512]
    attn_kernel<<<dim3(NSEQ / 64, NHEADS, 4), 256, attn_smem>>>(qkv, attn);

    // 3) IBPP branch -> g_cat[:, 512:768]
    ib_kernel<<<TOKENS * 16 / 256, 256>>>(x, w_in, b_in, w_out, b_out, cat);

    // 4) merged = attn @ w_merge + b_merge -> g_cat[:, 0:512]
    gemm_bias<<<dim3(MDIM / 64, TOKENS / 64), 256>>>(
        attn, MDIM, w_merge, MDIM, b_merge, cat, CATD, TOKENS, MDIM, MDIM);

    // 5) out = g_cat @ w_proj + b_proj    [8192,512] K=768
    gemm_bias<<<dim3(MDIM / 64, TOKENS / 64), 256>>>(
        cat, CATD, w_proj, MDIM, b_proj, out, MDIM, TOKENS, MDIM, CATD);
}

// round 7
// speedup vs baseline: 1.0010x; 1.0010x over previous
#include <cuda_runtime.h>

#define TOKENS 8192
#define INDIM  256
#define MDIM   512
#define QKV3   1536
#define NHEADS 8
#define DHEAD  64
#define NSEQ   2048
#define CATD   768
#define SCALE  0.125f

// ---------------- scratch (device globals; no allocations allowed) --------
__device__ float g_qkv [TOKENS * QKV3];   // 50.3 MB
__device__ float g_attn[TOKENS * MDIM];   // 16.8 MB
__device__ float g_cat [TOKENS * CATD];   // 25.2 MB

// ---------------- generic tiled fp32 GEMM: C = A @ B + bias ---------------
// A: [M,K] row-major (lda), B: [K,N] row-major (ldb), C: [M,N] (ldc)
// BM=BN=64, BK=16, 256 threads, 4x4 per thread.
__global__ __launch_bounds__(256) void gemm_bias(
    const float* __restrict__ A, int lda,
    const float* __restrict__ B, int ldb,
    const float* __restrict__ bias,
    float* __restrict__ C, int ldc,
    int M, int N, int K)
{
    __shared__ float As[16][65];   // transposed: As[k][m], padded
    __shared__ float Bs[16][64];   // Bs[k][n]

    const int tid = threadIdx.x;
    const int tr  = tid >> 4;      // 0..15 -> output rows tr*4..tr*4+3
    const int tc  = tid & 15;      // 0..15 -> output cols tc*4..tc*4+3
    const int m0  = blockIdx.y * 64;
    const int n0  = blockIdx.x * 64;

    // A tile load: 64 rows x 16 cols, one float4 per thread
    const int a_row = tid >> 2;          // 0..63
    const int a_col = (tid & 3) * 4;     // 0,4,8,12
    // B tile load: 16 rows x 64 cols, one float4 per thread
    const int b_row = tid >> 4;          // 0..15
    const int b_col = (tid & 15) * 4;    // 0..60

    const float* Aptr = A + (size_t)(m0 + a_row) * lda + a_col;
    const float* Bptr = B + (size_t)b_row * ldb + n0 + b_col;

    float acc[4][4];
#pragma unroll
    for (int i = 0; i < 4; i++)
#pragma unroll
        for (int j = 0; j < 4; j++) acc[i][j] = 0.f;

    for (int k0 = 0; k0 < K; k0 += 16) {
        float4 av = *(const float4*)(Aptr + k0);
        float4 bv = *(const float4*)(Bptr + (size_t)k0 * ldb);
        As[a_col + 0][a_row] = av.x;
        As[a_col + 1][a_row] = av.y;
        As[a_col + 2][a_row] = av.z;
        As[a_col + 3][a_row] = av.w;
        *(float4*)&Bs[b_row][b_col] = bv;
        __syncthreads();

#pragma unroll
        for (int kk = 0; kk < 16; kk++) {
            float a0 = As[kk][tr * 4 + 0];
            float a1 = As[kk][tr * 4 + 1];
            float a2 = As[kk][tr * 4 + 2];
            float a3 = As[kk][tr * 4 + 3];
            float4 b4 = *(const float4*)&Bs[kk][tc * 4];
            acc[0][0] += a0 * b4.x; acc[0][1] += a0 * b4.y; acc[0][2] += a0 * b4.z; acc[0][3] += a0 * b4.w;
            acc[1][0] += a1 * b4.x; acc[1][1] += a1 * b4.y; acc[1][2] += a1 * b4.z; acc[1][3] += a1 * b4.w;
            acc[2][0] += a2 * b4.x; acc[2][1] += a2 * b4.y; acc[2][2] += a2 * b4.z; acc[2][3] += a2 * b4.w;
            acc[3][0] += a3 * b4.x; acc[3][1] += a3 * b4.y; acc[3][2] += a3 * b4.z; acc[3][3] += a3 * b4.w;
        }
        __syncthreads();
    }

    const float bx = bias[n0 + tc * 4 + 0];
    const float by = bias[n0 + tc * 4 + 1];
    const float bz = bias[n0 + tc * 4 + 2];
    const float bw = bias[n0 + tc * 4 + 3];
#pragma unroll
    for (int i = 0; i < 4; i++) {
        float4 o;
        o.x = acc[i][0] + bx;
        o.y = acc[i][1] + by;
        o.z = acc[i][2] + bz;
        o.w = acc[i][3] + bw;
        *(float4*)&C[(size_t)(m0 + tr * 4 + i) * ldc + n0 + tc * 4] = o;
    }
}

// ---------------- flash attention (fp32, 64x64 tiles) ---------------------
// qkv row layout: [ q(512) | k(512) | v(512) ], head h at col h*64.
// grid: (NSEQ/64, NHEADS, B), 256 threads. Online softmax.
__global__ __launch_bounds__(256) void attn_kernel(
    const float* __restrict__ qkv, float* __restrict__ outp)
{
    extern __shared__ float sm[];
    float* Qs = sm;                 // [64][65]
    float* KP = sm + 64 * 65;       // K tile, then reused as P tile [64][65]
    float* Vs = sm + 2 * 64 * 65;   // [64][65]

    const int tid = threadIdx.x;
    const int tr  = tid >> 4;       // rows tr*4..+3
    const int tc  = tid & 15;       // cols tc*4..+3
    const int q0  = blockIdx.x * 64;
    const int h   = blockIdx.y;
    const int b   = blockIdx.z;
    const size_t rowbase = (size_t)b * NSEQ;

    // ---- load Q tile [64 x 64] ----
    const float* qptr = qkv + (rowbase + q0) * QKV3 + h * DHEAD;
#pragma unroll
    for (int u = 0; u < 4; u++) {
        int idx = tid + u * 256;
        int r = idx >> 4, c = (idx & 15) * 4;
        float4 v = *(const float4*)(qptr + (size_t)r * QKV3 + c);
        Qs[r * 65 + c + 0] = v.x; Qs[r * 65 + c + 1] = v.y;
        Qs[r * 65 + c + 2] = v.z; Qs[r * 65 + c + 3] = v.w;
    }

    float m[4], l[4], acc[4][4];
#pragma unroll
    for (int i = 0; i < 4; i++) {
        m[i] = -1e30f; l[i] = 0.f;
#pragma unroll
        for (int j = 0; j < 4; j++) acc[i][j] = 0.f;
    }
    __syncthreads();

    for (int t = 0; t < NSEQ; t += 64) {
        // ---- load K and V tiles ----
        const float* kptr = qkv + (rowbase + t) * QKV3 + MDIM + h * DHEAD;
        const float* vptr = qkv + (rowbase + t) * QKV3 + 2 * MDIM + h * DHEAD;
#pragma unroll
        for (int u = 0; u < 4; u++) {
            int idx = tid + u * 256;
            int r = idx >> 4, c = (idx & 15) * 4;
            float4 kv4 = *(const float4*)(kptr + (size_t)r * QKV3 + c);
            KP[r * 65 + c + 0] = kv4.x; KP[r * 65 + c + 1] = kv4.y;
            KP[r * 65 + c + 2] = kv4.z; KP[r * 65 + c + 3] = kv4.w;
            float4 vv4 = *(const float4*)(vptr + (size_t)r * QKV3 + c);
            Vs[r * 65 + c + 0] = vv4.x; Vs[r * 65 + c + 1] = vv4.y;
            Vs[r * 65 + c + 2] = vv4.z; Vs[r * 65 + c + 3] = vv4.w;
        }
        __syncthreads();

        // ---- S = Q @ K^T (4x4 per thread) ----
        float s[4][4];
#pragma unroll
        for (int i = 0; i < 4; i++)
#pragma unroll
            for (int j = 0; j < 4; j++) s[i][j] = 0.f;

#pragma unroll 8
        for (int d = 0; d < 64; d++) {
            float a0 = Qs[(tr * 4 + 0) * 65 + d];
            float a1 = Qs[(tr * 4 + 1) * 65 + d];
            float a2 = Qs[(tr * 4 + 2) * 65 + d];
            float a3 = Qs[(tr * 4 + 3) * 65 + d];
            float b0 = KP[(tc * 4 + 0) * 65 + d];
            float b1 = KP[(tc * 4 + 1) * 65 + d];
            float b2 = KP[(tc * 4 + 2) * 65 + d];
            float b3 = KP[(tc * 4 + 3) * 65 + d];
            s[0][0] += a0 * b0; s[0][1] += a0 * b1; s[0][2] += a0 * b2; s[0][3] += a0 * b3;
            s[1][0] += a1 * b0; s[1][1] += a1 * b1; s[1][2] += a1 * b2; s[1][3] += a1 * b3;
            s[2][0] += a2 * b0; s[2][1] += a2 * b1; s[2][2] += a2 * b2; s[2][3] += a2 * b3;
            s[3][0] += a3 * b0; s[3][1] += a3 * b1; s[3][2] += a3 * b2; s[3][3] += a3 * b3;
        }

        // ---- online softmax over rows (16 lanes share one row group) ----
#pragma unroll
        for (int i = 0; i < 4; i++) {
#pragma unroll
            for (int j = 0; j < 4; j++) s[i][j] *= SCALE;
            float tm = fmaxf(fmaxf(s[i][0], s[i][1]), fmaxf(s[i][2], s[i][3]));
#pragma unroll
            for (int off = 8; off > 0; off >>= 1)
                tm = fmaxf(tm, __shfl_xor_sync(0xffffffffu, tm, off));
            float mn = fmaxf(m[i], tm);
            float al = __expf(m[i] - mn);
            float rs = 0.f;
#pragma unroll
            for (int j = 0; j < 4; j++) {
                s[i][j] = __expf(s[i][j] - mn);
                rs += s[i][j];
            }
#pragma unroll
            for (int off = 8; off > 0; off >>= 1)
                rs += __shfl_xor_sync(0xffffffffu, rs, off);
            l[i] = l[i] * al + rs;
#pragma unroll
            for (int j = 0; j < 4; j++) acc[i][j] *= al;
            m[i] = mn;
        }

        __syncthreads();   // all K reads done before overwriting with P
#pragma unroll
        for (int i = 0; i < 4; i++)
#pragma unroll
            for (int j = 0; j < 4; j++)
                KP[(tr * 4 + i) * 65 + tc * 4 + j] = s[i][j];
        __syncthreads();

        // ---- O += P @ V ----
#pragma unroll 8
        for (int kv = 0; kv < 64; kv++) {
            float p0 = KP[(tr * 4 + 0) * 65 + kv];
            float p1 = KP[(tr * 4 + 1) * 65 + kv];
            float p2 = KP[(tr * 4 + 2) * 65 + kv];
            float p3 = KP[(tr * 4 + 3) * 65 + kv];
            float v0 = Vs[kv * 65 + tc * 4 + 0];
            float v1 = Vs[kv * 65 + tc * 4 + 1];
            float v2 = Vs[kv * 65 + tc * 4 + 2];
            float v3 = Vs[kv * 65 + tc * 4 + 3];
            acc[0][0] += p0 * v0; acc[0][1] += p0 * v1; acc[0][2] += p0 * v2; acc[0][3] += p0 * v3;
            acc[1][0] += p1 * v0; acc[1][1] += p1 * v1; acc[1][2] += p1 * v2; acc[1][3] += p1 * v3;
            acc[2][0] += p2 * v0; acc[2][1] += p2 * v1; acc[2][2] += p2 * v2; acc[2][3] += p2 * v3;
            acc[3][0] += p3 * v0; acc[3][1] += p3 * v1; acc[3][2] += p3 * v2; acc[3][3] += p3 * v3;
        }
        __syncthreads();
    }

    // ---- epilogue: normalize + write [b, n, h*64 + c] ----
    float* obase = outp + (rowbase + q0) * MDIM + h * DHEAD;
#pragma unroll
    for (int i = 0; i < 4; i++) {
        float inv = 1.0f / l[i];
        float4 o;
        o.x = acc[i][0] * inv;
        o.y = acc[i][1] * inv;
        o.z = acc[i][2] * inv;
        o.w = acc[i][3] * inv;
        *(float4*)(obase + (size_t)(tr * 4 + i) * MDIM + tc * 4) = o;
    }
}

// ---------------- IBPP branch: silu(xr @ w_in + b_in) @ w_out + b_out -----
// one thread per (token, row-of-16); writes into g_cat cols [512, 768)
__global__ __launch_bounds__(256) void ib_kernel(
    const float* __restrict__ x,
    const float* __restrict__ w_in, const float* __restrict__ b_in,
    const float* __restrict__ w_out, const float* __restrict__ b_out,
    float* __restrict__ cat)
{
    __shared__ float wi[16][16], wo[16][16], bi[16], bo[16];
    const int tid = threadIdx.x;
    wi[tid >> 4][tid & 15] = w_in[tid];
    wo[tid >> 4][tid & 15] = w_out[tid];
    if (tid < 16) { bi[tid] = b_in[tid]; bo[tid] = b_out[tid]; }
    __syncthreads();

    const int gid = blockIdx.x * 256 + tid;
    const int token = gid >> 4;
    const int i = gid & 15;

    const float* xr = x + (size_t)token * INDIM + i * 16;
    float xv[16];
#pragma unroll
    for (int k = 0; k < 16; k++) xv[k] = xr[k];

    float t1[16];
#pragma unroll
    for (int j = 0; j < 16; j++) {
        float s = bi[j];
#pragma unroll
        for (int k = 0; k < 16; k++) s += xv[k] * wi[k][j];
        t1[j] = s / (1.0f + __expf(-s));   // silu
    }

    float* o = cat + (size_t)token * CATD + MDIM + i * 16;
#pragma unroll
    for (int j = 0; j < 16; j++) {
        float s = bo[j];
#pragma unroll
        for (int k = 0; k < 16; k++) s += t1[k] * wo[k][j];
        o[j] = s;
    }
}

// ---------------- launch ---------------------------------------------------
extern "C" void kernel_launch(void* const* d_in, const int* in_sizes, int n_in,
                              void* d_out, int out_size)
{
    const float* x       = (const float*)d_in[0];
    const float* w_qkv   = (const float*)d_in[1];
    const float* b_qkv   = (const float*)d_in[2];
    const float* w_in    = (const float*)d_in[3];
    const float* b_in    = (const float*)d_in[4];
    const float* w_out   = (const float*)d_in[5];
    const float* b_out   = (const float*)d_in[6];
    const float* w_merge = (const float*)d_in[7];
    const float* b_merge = (const float*)d_in[8];
    const float* w_proj  = (const float*)d_in[9];
    const float* b_proj  = (const float*)d_in[10];
    float* out = (float*)d_out;

    float *qkv, *attn, *cat;
    cudaGetSymbolAddress((void**)&qkv,  g_qkv);
    cudaGetSymbolAddress((void**)&attn, g_attn);
    cudaGetSymbolAddress((void**)&cat,  g_cat);

    const int attn_smem = 3 * 64 * 65 * (int)sizeof(float);   // 49920 B
    cudaFuncSetAttribute(attn_kernel,
                         cudaFuncAttributeMaxDynamicSharedMemorySize, attn_smem);

    // 1) QKV = x @ w_qkv + b_qkv          [8192,1536] K=256
    gemm_bias<<<dim3(QKV3 / 64, TOKENS / 64), 256>>>(
        x, INDIM, w_qkv, QKV3, b_qkv, qkv, QKV3, TOKENS, QKV3, INDIM);

    // 2) flash attention -> g_attn        [8192,512]
    attn_kernel<<<dim3(NSEQ / 64, NHEADS, 4), 256, attn_smem>>>(qkv, attn);

    // 3) IBPP branch -> g_cat[:, 512:768]
    ib_kernel<<<TOKENS * 16 / 256, 256>>>(x, w_in, b_in, w_out, b_out, cat);

    // 4) merged = attn @ w_merge + b_merge -> g_cat[:, 0:512]
    gemm_bias<<<dim3(MDIM / 64, TOKENS / 64), 256>>>(
        attn, MDIM, w_merge, MDIM, b_merge, cat, CATD, TOKENS, MDIM, MDIM);

    // 5) out = g_cat @ w_proj + b_proj    [8192,512] K=768
    gemm_bias<<<dim3(MDIM / 64, TOKENS / 64), 256>>>(
        cat, CATD, w_proj, MDIM, b_proj, out, MDIM, TOKENS, MDIM, CATD);
}